// round 2
// baseline (speedup 1.0000x reference)
#include <cuda_runtime.h>
#include <math.h>

#define BB 2
#define QQ 75
#define NN 5
#define KK 1
#define TT 196
#define CC 384
#define HH 1536
#define KT (KK*TT)
#define BQ (BB*QQ)
#define TEMPF 10.0f

#define MCH 7          // t-chunks for mean kernel (28 rows each)
#define SCH 5          // t-chunks for shot kernel (40/36 rows)
#define HCH 8          // hidden chunks for MLP (192 units each)
#define HCW (HH/HCH)   // 192
#define TH  (TT/2)     // 98, t-half for main kernel

// ---------------- scratch (no allocation allowed) ----------------
__device__ float g_mean_part[BB*NN*MCH*CC];
__device__ float g_cls_mean[BB*NN*CC];
__device__ float g_task_mean[BB*CC];
__device__ float g_mlp_part[(BB + BB*NN)*HCH*CC];
__device__ float g_wt[BB*CC];
__device__ float g_wc[BB*NN*CC];
__device__ float g_ns[BB*NN*KT];
__device__ float g_shot_part[BB*NN*SCH*CC];
__device__ float g_xs_hat[BB*NN*CC];
__device__ float g_xs2_hat[BB*NN*CC];
__device__ float g_accq_part[2*BQ*NN*CC];
__device__ float g_mx_part[2*BQ*NN];

template<int NV>
__device__ __forceinline__ void warpRed(float* v) {
#pragma unroll
    for (int off = 16; off; off >>= 1) {
#pragma unroll
        for (int k = 0; k < NV; k++)
            v[k] += __shfl_xor_sync(0xffffffffu, v[k], off);
    }
}

__device__ __forceinline__ float sigm(float x) {
    return 1.0f / (1.0f + __expf(-x));
}

// ---------------- K1: partial shot sums over t-chunks ----------------
__global__ __launch_bounds__(CC, 4) void kMeanPart(const float* __restrict__ fshot) {
    int bn = blockIdx.x / MCH, ch = blockIdx.x % MCH, c = threadIdx.x;
    int t0 = ch * 28;
    const float* p = fshot + ((size_t)bn * KT + t0) * CC + c;
    float s = 0.0f;
#pragma unroll 4
    for (int t = 0; t < 28; t++) s += p[(size_t)t * CC];
    g_mean_part[(bn * MCH + ch) * CC + c] = s;
}

// ---------------- K2: combine -> cls_mean, task_mean ----------------
__global__ __launch_bounds__(CC, 4) void kCombineMean() {
    int rid = blockIdx.x, c = threadIdx.x;
    if (rid < BB * NN) {
        float s = 0.0f;
#pragma unroll
        for (int ch = 0; ch < MCH; ch++) s += g_mean_part[(rid * MCH + ch) * CC + c];
        g_cls_mean[rid * CC + c] = s * (1.0f / KT);
    } else {
        int b = rid - BB * NN;
        float s = 0.0f;
#pragma unroll
        for (int n = 0; n < NN; n++)
#pragma unroll
            for (int ch = 0; ch < MCH; ch++)
                s += g_mean_part[((b * NN + n) * MCH + ch) * CC + c];
        g_task_mean[b * CC + c] = s * (1.0f / (KT * NN));
    }
}

// ---------------- K3: MLP partials. grid = 12 rows x 8 hidden-chunks ----------------
__global__ __launch_bounds__(CC, 2) void kMLPpart(
    const float* __restrict__ w1t, const float* __restrict__ b1t,
    const float* __restrict__ w2t,
    const float* __restrict__ w1c, const float* __restrict__ b1c,
    const float* __restrict__ w2c) {
    __shared__ float sx[CC];
    __shared__ float hp[2 * HCW];
    __shared__ float hid[HCW];
    int row = blockIdx.x / HCH, ch = blockIdx.x % HCH, tid = threadIdx.x;
    const float *in, *w1, *b1, *w2;
    if (row < BB) {
        in = g_task_mean + row * CC; w1 = w1t; b1 = b1t; w2 = w2t;
    } else {
        int r = row - BB;
        in = g_cls_mean + r * CC; w1 = w1c; b1 = b1c; w2 = w2c;
    }
    sx[tid] = in[tid];
    __syncthreads();

    int half = tid / HCW;          // 0 or 1 (c-range split)
    int jj = tid % HCW;            // hidden unit within chunk
    int j0 = ch * HCW;
    float h = 0.0f;
    const float* w1p = w1 + (size_t)(half * HCW) * HH + j0 + jj;
#pragma unroll 4
    for (int c = 0; c < HCW; c++) h += sx[half * HCW + c] * w1p[(size_t)c * HH];
    hp[half * HCW + jj] = h;
    __syncthreads();
    if (tid < HCW) hid[tid] = fmaxf(hp[tid] + hp[HCW + tid] + b1[j0 + tid], 0.0f);
    __syncthreads();

    float o = 0.0f;
    const float* w2p = w2 + (size_t)j0 * CC + tid;
#pragma unroll 4
    for (int j = 0; j < HCW; j++) o += hid[j] * w2p[(size_t)j * CC];
    g_mlp_part[(size_t)blockIdx.x * CC + tid] = o;
}

// ---------------- K3b: finish MLPs (bias + sigmoid) ----------------
__global__ __launch_bounds__(CC, 4) void kMLPfin(
    const float* __restrict__ b2t, const float* __restrict__ b2c) {
    int row = blockIdx.x, tid = threadIdx.x;
    float o = (row < BB) ? b2t[tid] : b2c[tid];
#pragma unroll
    for (int ch = 0; ch < HCH; ch++) o += g_mlp_part[(size_t)(row * HCH + ch) * CC + tid];
    if (row < BB) g_wt[row * CC + tid] = o;
    else          g_wc[(row - BB) * CC + tid] = sigm(o);
}

// ---------------- K4: shot-side pass over t-chunks ----------------
__global__ __launch_bounds__(CC, 2) void kShotPart(const float* __restrict__ fshot) {
    __shared__ __align__(16) float vv[CC];
    __shared__ float accs[CC];
    int bn = blockIdx.x / SCH, ch = blockIdx.x % SCH;
    int b = bn / NN, tid = threadIdx.x;
    int w = tid >> 5, lane = tid & 31;
    int t0 = ch * 40, t1 = min(KT, t0 + 40);

    vv[tid]   = g_wc[bn * CC + tid] * g_wt[b * CC + tid];
    accs[tid] = 0.0f;
    __syncthreads();

    float acc[12];
#pragma unroll
    for (int e = 0; e < 12; e++) acc[e] = 0.0f;

    for (int t = t0 + w; t < t1; t += 12) {
        const float* fp = fshot + ((size_t)bn * KT + t) * CC + 4 * lane;
        float fv[12];
#pragma unroll
        for (int j = 0; j < 3; j++) {
            float4 u = *(const float4*)(fp + 128 * j);
            fv[4 * j] = u.x; fv[4 * j + 1] = u.y; fv[4 * j + 2] = u.z; fv[4 * j + 3] = u.w;
        }
        float r[2] = {0.0f, 0.0f};
#pragma unroll
        for (int j = 0; j < 3; j++) {
            float4 u = *(const float4*)(&vv[128 * j + 4 * lane]);
            r[0] += fv[4*j]*fv[4*j] + fv[4*j+1]*fv[4*j+1] + fv[4*j+2]*fv[4*j+2] + fv[4*j+3]*fv[4*j+3];
            r[1] += fv[4*j]*u.x + fv[4*j+1]*u.y + fv[4*j+2]*u.z + fv[4*j+3]*u.w;
        }
        warpRed<2>(r);
        if (lane == 0) g_ns[bn * KT + t] = sqrtf(r[0]);
        float ms = sigm(r[1]);
#pragma unroll
        for (int e = 0; e < 12; e++) acc[e] += fv[e] * ms;
    }
#pragma unroll
    for (int e = 0; e < 12; e++) {
        int c = 128 * (e >> 2) + (lane << 2) + (e & 3);
        atomicAdd(&accs[c], acc[e]);
    }
    __syncthreads();
    g_shot_part[(size_t)blockIdx.x * CC + tid] = accs[tid];
}

// ---------------- K5: finish shot prototypes ----------------
__global__ __launch_bounds__(CC, 4) void kShotFin(const float* __restrict__ x_shot) {
    __shared__ float cw[12][2];
    __shared__ float tot[2];
    int bn = blockIdx.x, tid = threadIdx.x;
    int w = tid >> 5, lane = tid & 31;

    float s = 0.0f;
#pragma unroll
    for (int ch = 0; ch < SCH; ch++) s += g_shot_part[(size_t)(bn * SCH + ch) * CC + tid];
    float xsr = g_wc[bn * CC + tid] * s * (1.0f / KT);
    float xm = 0.0f;
#pragma unroll
    for (int k = 0; k < KK; k++) xm += x_shot[((size_t)bn * KK + k) * CC + tid];
    xm *= (1.0f / KK);

    float r2[2] = {xsr * xsr, xm * xm};
    warpRed<2>(r2);
    if (lane == 0) { cw[w][0] = r2[0]; cw[w][1] = r2[1]; }
    __syncthreads();
    if (tid < 2) {
        float ss = 0.0f;
        for (int ww = 0; ww < 12; ww++) ss += cw[ww][tid];
        tot[tid] = ss;
    }
    __syncthreads();
    g_xs_hat[bn * CC + tid]  = xsr / (1e-16f + sqrtf(tot[0]));
    g_xs2_hat[bn * CC + tid] = xm / fmaxf(sqrtf(tot[1]), 1e-12f);
}

// ---------------- K6: main fused pass, per (b,q) x t-half ----------------
__global__ __launch_bounds__(256, 2) void kMainPart(
    const float* __restrict__ fshot, const float* __restrict__ fq) {
    __shared__ __align__(16) float vv[NN * CC];
    __shared__ float accq[NN * CC];
    __shared__ float nss[NN * TH];
    __shared__ float wmax[8 * NN];

    int chunk = blockIdx.x & 1, bq = blockIdx.x >> 1;
    int b = bq / QQ, tid = threadIdx.x;
    int w = tid >> 5, lane = tid & 31;
    int t0 = chunk * TH, t1 = t0 + TH;

    for (int c = tid; c < NN * CC; c += 256) {
        int n = c / CC, cc = c % CC;
        vv[c] = g_wc[(b * NN + n) * CC + cc] * g_wt[b * CC + cc];
        accq[c] = 0.0f;
    }
    for (int i = tid; i < NN * TH; i += 256) {
        int n = i / TH, ttt = i % TH;
        nss[i] = g_ns[(b * NN + n) * KT + t0 + ttt];
    }
    __syncthreads();

    float acc[NN * 12];
#pragma unroll
    for (int e = 0; e < NN * 12; e++) acc[e] = 0.0f;
    float mx[NN];
#pragma unroll
    for (int n = 0; n < NN; n++) mx[n] = -3.4e38f;

    for (int t = t0 + w; t < t1; t += 8) {
        const float* fp = fq + (((size_t)bq) * TT + t) * CC + 4 * lane;
        float fv[12];
#pragma unroll
        for (int j = 0; j < 3; j++) {
            float4 u = *(const float4*)(fp + 128 * j);
            fv[4 * j] = u.x; fv[4 * j + 1] = u.y; fv[4 * j + 2] = u.z; fv[4 * j + 3] = u.w;
        }
        float r[11];
#pragma unroll
        for (int k = 0; k < 11; k++) r[k] = 0.0f;
#pragma unroll
        for (int e = 0; e < 12; e++) r[0] += fv[e] * fv[e];
#pragma unroll
        for (int n = 0; n < NN; n++) {
            const float* fsp = fshot + (((size_t)(b * NN + n)) * KT + t) * CC + 4 * lane;
#pragma unroll
            for (int j = 0; j < 3; j++) {
                float4 u = *(const float4*)(fsp + 128 * j);
                r[1 + n] += fv[4*j]*u.x + fv[4*j+1]*u.y + fv[4*j+2]*u.z + fv[4*j+3]*u.w;
            }
        }
#pragma unroll
        for (int n = 0; n < NN; n++) {
#pragma unroll
            for (int j = 0; j < 3; j++) {
                float4 u = *(const float4*)(&vv[n * CC + 128 * j + 4 * lane]);
                r[6 + n] += fv[4*j]*u.x + fv[4*j+1]*u.y + fv[4*j+2]*u.z + fv[4*j+3]*u.w;
            }
        }
        warpRed<11>(r);
        float nq = sqrtf(r[0]);
        int trel = t - t0;
#pragma unroll
        for (int n = 0; n < NN; n++) {
            float den = fmaxf(nq * nss[n * TH + trel], 1e-8f);
            mx[n] = fmaxf(mx[n], r[1 + n] / den);
            float mq = sigm(r[6 + n]);
#pragma unroll
            for (int e = 0; e < 12; e++) acc[n * 12 + e] += fv[e] * mq;
        }
    }

#pragma unroll
    for (int n = 0; n < NN; n++) {
#pragma unroll
        for (int e = 0; e < 12; e++) {
            int c = 128 * (e >> 2) + (lane << 2) + (e & 3);
            atomicAdd(&accq[n * CC + c], acc[n * 12 + e]);
        }
    }
    if (lane == 0) {
#pragma unroll
        for (int n = 0; n < NN; n++) wmax[w * NN + n] = mx[n];
    }
    __syncthreads();

    size_t base = ((size_t)(chunk * BQ + bq)) * NN * CC;
    for (int i = tid; i < NN * CC; i += 256)
        g_accq_part[base + i] = accq[i];
    if (tid < NN) {
        float m = -3.4e38f;
        for (int ww = 0; ww < 8; ww++) m = fmaxf(m, wmax[ww * NN + tid]);
        g_mx_part[(chunk * BQ + bq) * NN + tid] = m;
    }
}

// ---------------- K7: combine + final outputs ----------------
__global__ __launch_bounds__(CC, 2) void kMainFin(
    const float* __restrict__ xq_in, float* __restrict__ out) {
    __shared__ float cw[12][16];
    __shared__ float tot[16];

    int bq = blockIdx.x, b = bq / QQ, tid = threadIdx.x;
    int w = tid >> 5, lane = tid & 31;

    if (tid == 0) {
        float s = 0.0f;
#pragma unroll
        for (int n = 0; n < NN; n++)
            s += fmaxf(g_mx_part[bq * NN + n], g_mx_part[(BQ + bq) * NN + n]);
        s *= (1.0f / NN);
        out[bq] = s;
        out[BQ + bq] = s;
    }

    float xqv = xq_in[(size_t)bq * CC + tid];
    float pv[16];
    pv[0] = xqv * xqv;
#pragma unroll
    for (int n = 0; n < NN; n++) {
        float a = g_accq_part[((size_t)bq * NN + n) * CC + tid]
                + g_accq_part[((size_t)(BQ + bq) * NN + n) * CC + tid];
        float xqr = g_wc[(b * NN + n) * CC + tid] * a * (1.0f / TT);
        pv[1 + n]  = xqv * g_xs2_hat[(b * NN + n) * CC + tid];
        pv[6 + n]  = xqr * xqr;
        pv[11 + n] = xqr * g_xs_hat[(b * NN + n) * CC + tid];
    }
    warpRed<16>(pv);
    if (lane == 0) {
#pragma unroll
        for (int k = 0; k < 16; k++) cw[w][k] = pv[k];
    }
    __syncthreads();
    if (tid < 16) {
        float s = 0.0f;
        for (int ww = 0; ww < 12; ww++) s += cw[ww][tid];
        tot[tid] = s;
    }
    __syncthreads();
    if (tid < NN) {
        float nq2 = sqrtf(tot[0]);
        out[2 * BQ + bq * NN + tid] = TEMPF * tot[1 + tid] / fmaxf(nq2, 1e-12f);
        out[2 * BQ + BQ * NN + bq * NN + tid] = tot[11 + tid] / (1e-16f + sqrtf(tot[6 + tid]));
    }
}

extern "C" void kernel_launch(void* const* d_in, const int* in_sizes, int n_in,
                              void* d_out, int out_size) {
    const float* feat_shot  = (const float*)d_in[0];
    const float* feat_query = (const float*)d_in[1];
    const float* x_shot     = (const float*)d_in[2];
    const float* x_query    = (const float*)d_in[3];
    const float* w1_task    = (const float*)d_in[4];
    const float* b1_task    = (const float*)d_in[5];
    const float* w2_task    = (const float*)d_in[6];
    const float* b2_task    = (const float*)d_in[7];
    const float* w1_cls     = (const float*)d_in[8];
    const float* b1_cls     = (const float*)d_in[9];
    const float* w2_cls     = (const float*)d_in[10];
    const float* b2_cls     = (const float*)d_in[11];
    float* out = (float*)d_out;

    kMeanPart<<<BB * NN * MCH, CC>>>(feat_shot);
    kCombineMean<<<BB * NN + BB, CC>>>();
    kMLPpart<<<(BB + BB * NN) * HCH, CC>>>(w1_task, b1_task, w2_task,
                                           w1_cls, b1_cls, w2_cls);
    kMLPfin<<<BB + BB * NN, CC>>>(b2_task, b2_cls);
    kShotPart<<<BB * NN * SCH, CC>>>(feat_shot);
    kShotFin<<<BB * NN, CC>>>(x_shot);
    kMainPart<<<BQ * 2, 256>>>(feat_shot, feat_query);
    kMainFin<<<BQ, CC>>>(x_query, out);
}

// round 3
// speedup vs baseline: 1.1742x; 1.1742x over previous
#include <cuda_runtime.h>
#include <math.h>

#define BB 2
#define QQ 75
#define NN 5
#define KK 1
#define TT 196
#define CC 384
#define HH 1536
#define KT 196
#define BQ 150
#define TEMPF 10.0f

#define MCH 7          // t-chunks for mean partials (28 rows)
#define SCH 5          // t-chunks for shot pass (40/36 rows)
#define HCH 8          // hidden chunks for MLP (192 units)
#define HCW 192
#define TQ 49          // t-quarter for main pass
#define NCHK 4
#define NW 12          // warps per block (384 threads)

// ---------------- persistent scratch ----------------
__device__ float g_mean_part[BB*NN*MCH*CC];
__device__ float g_mlp_part[(BB + BB*NN)*HCH*CC];
__device__ float g_wt[BB*CC];
__device__ float g_wc[BB*NN*CC];
__device__ float g_ns[BB*NN*KT];
__device__ float g_shot_part[BB*NN*SCH*CC];
__device__ float g_xs_hat[BB*NN*CC];
__device__ float g_xs2_hat[BB*NN*CC];
__device__ float g_accq_part[NCHK*BQ*NN*CC];
__device__ float g_mx_part[NCHK*BQ*NN];
__device__ unsigned g_bar_cnt;   // zero-init; returns to 0 after every barrier
__device__ unsigned g_bar_gen;   // monotonic across replays (wrap-safe)

template<int NV>
__device__ __forceinline__ void warpRed(float* v) {
#pragma unroll
    for (int off = 16; off; off >>= 1) {
#pragma unroll
        for (int k = 0; k < NV; k++)
            v[k] += __shfl_xor_sync(0xffffffffu, v[k], off);
    }
}

__device__ __forceinline__ float sigm(float x) {
    return 1.0f / (1.0f + __expf(-x));
}

// device-wide barrier: all blocks guaranteed co-resident (grid sized by occupancy API)
__device__ __forceinline__ void gridBar() {
    __syncthreads();
    if (threadIdx.x == 0) {
        __threadfence();
        unsigned gen = *(volatile unsigned*)&g_bar_gen;
        if (atomicAdd(&g_bar_cnt, 1u) == gridDim.x - 1u) {
            g_bar_cnt = 0u;
            __threadfence();
            atomicAdd(&g_bar_gen, 1u);
        } else {
            while (*(volatile unsigned*)&g_bar_gen == gen) __nanosleep(64);
        }
        __threadfence();
    }
    __syncthreads();
}

struct SmemMain { float vv[NN*CC]; float accq[NN*CC]; float nss[NN*TQ]; float wmax[NW*NN]; };
struct SmemMLP  { float sx[CC]; float hp[2*HCW]; float hid[HCW]; };
struct SmemShot { float vv[CC]; float accs[CC]; };
struct SmemRed  { float cw[NW][16]; float tot[16]; };
union SmemU { SmemMain m; SmemMLP p; SmemShot s; SmemRed r; };

__global__ __launch_bounds__(384, 1) void kFused(
    const float* __restrict__ fshot, const float* __restrict__ fq,
    const float* __restrict__ x_shot, const float* __restrict__ xq_in,
    const float* __restrict__ w1t, const float* __restrict__ b1t,
    const float* __restrict__ w2t, const float* __restrict__ b2t,
    const float* __restrict__ w1c, const float* __restrict__ b1c,
    const float* __restrict__ w2c, const float* __restrict__ b2c,
    float* __restrict__ out) {
    __shared__ SmemU sm;
    const int tid = threadIdx.x;
    const int w = tid >> 5, lane = tid & 31;

    // ============ Phase 1: shot mean partials + plain prototype ============
    for (int task = blockIdx.x; task < BB*NN*MCH + BB*NN; task += gridDim.x) {
        if (task < BB*NN*MCH) {
            int bn = task / MCH, ch = task % MCH;
            int t0 = ch * 28;
            const float* p = fshot + ((size_t)bn * KT + t0) * CC + tid;
            float s = 0.0f;
#pragma unroll 4
            for (int t = 0; t < 28; t++) s += p[(size_t)t * CC];
            g_mean_part[(bn * MCH + ch) * CC + tid] = s;
        } else {
            int bn = task - BB*NN*MCH;
            __syncthreads();
            float xm = x_shot[(size_t)bn * CC + tid];  // KK=1
            float r[1] = {xm * xm};
            warpRed<1>(r);
            if (lane == 0) sm.r.cw[w][0] = r[0];
            __syncthreads();
            float tot = 0.0f;
#pragma unroll
            for (int ww = 0; ww < NW; ww++) tot += sm.r.cw[ww][0];
            g_xs2_hat[bn * CC + tid] = xm / fmaxf(sqrtf(tot), 1e-12f);
            __syncthreads();
        }
    }
    gridBar();

    // ============ Phase 2: MLP partials (means reconstructed inline) ============
    for (int task = blockIdx.x; task < (BB + BB*NN) * HCH; task += gridDim.x) {
        int row = task / HCH, ch = task % HCH;
        const float *w1, *b1, *w2;
        __syncthreads();
        if (row < BB) {
            w1 = w1t; b1 = b1t; w2 = w2t;
            float s = 0.0f;
#pragma unroll
            for (int n = 0; n < NN; n++)
#pragma unroll
                for (int c2 = 0; c2 < MCH; c2++)
                    s += g_mean_part[((row * NN + n) * MCH + c2) * CC + tid];
            sm.p.sx[tid] = s * (1.0f / (KT * NN));
        } else {
            int r = row - BB;
            w1 = w1c; b1 = b1c; w2 = w2c;
            float s = 0.0f;
#pragma unroll
            for (int c2 = 0; c2 < MCH; c2++)
                s += g_mean_part[(r * MCH + c2) * CC + tid];
            sm.p.sx[tid] = s * (1.0f / KT);
        }
        __syncthreads();

        int half = tid / HCW, jj = tid % HCW, j0 = ch * HCW;
        float h = 0.0f;
        const float* w1p = w1 + (size_t)(half * HCW) * HH + j0 + jj;
#pragma unroll 4
        for (int c = 0; c < HCW; c++) h += sm.p.sx[half * HCW + c] * w1p[(size_t)c * HH];
        sm.p.hp[half * HCW + jj] = h;
        __syncthreads();
        if (tid < HCW) sm.p.hid[tid] = fmaxf(sm.p.hp[tid] + sm.p.hp[HCW + tid] + b1[j0 + tid], 0.0f);
        __syncthreads();

        float o = 0.0f;
        const float* w2p = w2 + (size_t)j0 * CC + tid;
#pragma unroll 4
        for (int j = 0; j < HCW; j++) o += sm.p.hid[j] * w2p[(size_t)j * CC];
        g_mlp_part[(size_t)task * CC + tid] = o;
        __syncthreads();
    }
    gridBar();

    // ============ Phase 3: shot pass (ns + map_s partials) + MLP finish ============
    for (int task = blockIdx.x; task < BB*NN*SCH + BB + BB*NN; task += gridDim.x) {
        if (task < BB*NN*SCH) {
            int bn = task / SCH, ch = task % SCH;
            int b = bn / NN;
            int t0 = ch * 40, t1 = min(KT, t0 + 40);
            __syncthreads();
            {   // vv = wc * wt reconstructed from MLP partials
                float ot = b2t[tid], oc = b2c[tid];
#pragma unroll
                for (int c2 = 0; c2 < HCH; c2++) {
                    ot += g_mlp_part[(size_t)(b * HCH + c2) * CC + tid];
                    oc += g_mlp_part[(size_t)((BB + bn) * HCH + c2) * CC + tid];
                }
                sm.s.vv[tid] = sigm(oc) * ot;
                sm.s.accs[tid] = 0.0f;
            }
            __syncthreads();

            float acc[12];
#pragma unroll
            for (int e = 0; e < 12; e++) acc[e] = 0.0f;
            for (int t = t0 + w; t < t1; t += NW) {
                const float* fp = fshot + ((size_t)bn * KT + t) * CC + 4 * lane;
                float fv[12];
#pragma unroll
                for (int j = 0; j < 3; j++) {
                    float4 u = *(const float4*)(fp + 128 * j);
                    fv[4*j] = u.x; fv[4*j+1] = u.y; fv[4*j+2] = u.z; fv[4*j+3] = u.w;
                }
                float r[2] = {0.0f, 0.0f};
#pragma unroll
                for (int j = 0; j < 3; j++) {
                    float4 u = *(const float4*)(&sm.s.vv[128 * j + 4 * lane]);
                    r[0] += fv[4*j]*fv[4*j] + fv[4*j+1]*fv[4*j+1] + fv[4*j+2]*fv[4*j+2] + fv[4*j+3]*fv[4*j+3];
                    r[1] += fv[4*j]*u.x + fv[4*j+1]*u.y + fv[4*j+2]*u.z + fv[4*j+3]*u.w;
                }
                warpRed<2>(r);
                if (lane == 0) g_ns[bn * KT + t] = sqrtf(r[0]);
                float ms = sigm(r[1]);
#pragma unroll
                for (int e = 0; e < 12; e++) acc[e] += fv[e] * ms;
            }
#pragma unroll
            for (int e = 0; e < 12; e++) {
                int c = 128 * (e >> 2) + (lane << 2) + (e & 3);
                atomicAdd(&sm.s.accs[c], acc[e]);
            }
            __syncthreads();
            g_shot_part[(size_t)task * CC + tid] = sm.s.accs[tid];
            __syncthreads();
        } else {
            int row = task - BB*NN*SCH;
            float o = (row < BB) ? b2t[tid] : b2c[tid];
#pragma unroll
            for (int c2 = 0; c2 < HCH; c2++) o += g_mlp_part[(size_t)(row * HCH + c2) * CC + tid];
            if (row < BB) g_wt[row * CC + tid] = o;
            else          g_wc[(row - BB) * CC + tid] = sigm(o);
        }
    }
    gridBar();

    // ============ Phase 4: reweighted prototype finish + main fused pass ============
    for (int task = blockIdx.x; task < BB*NN + BQ*NCHK; task += gridDim.x) {
        if (task < BB*NN) {
            int bn = task;
            __syncthreads();
            float s = 0.0f;
#pragma unroll
            for (int ch = 0; ch < SCH; ch++) s += g_shot_part[(size_t)(bn * SCH + ch) * CC + tid];
            float xsr = g_wc[bn * CC + tid] * s * (1.0f / KT);
            float r[1] = {xsr * xsr};
            warpRed<1>(r);
            if (lane == 0) sm.r.cw[w][0] = r[0];
            __syncthreads();
            float tot = 0.0f;
#pragma unroll
            for (int ww = 0; ww < NW; ww++) tot += sm.r.cw[ww][0];
            g_xs_hat[bn * CC + tid] = xsr / (1e-16f + sqrtf(tot));
            __syncthreads();
        } else {
            int m = task - BB*NN;
            int bq = m >> 2, chunk = m & 3;
            int b = bq / QQ;
            int t0 = chunk * TQ;
            __syncthreads();
            {
                float wtb = g_wt[b * CC + tid];
#pragma unroll
                for (int n = 0; n < NN; n++) {
                    sm.m.vv[n * CC + tid] = g_wc[(b * NN + n) * CC + tid] * wtb;
                    sm.m.accq[n * CC + tid] = 0.0f;
                }
                for (int i = tid; i < NN * TQ; i += 384) {
                    int n = i / TQ, tt = i % TQ;
                    sm.m.nss[i] = g_ns[(b * NN + n) * KT + t0 + tt];
                }
            }
            __syncthreads();

            float acc[NN * 12];
#pragma unroll
            for (int e = 0; e < NN * 12; e++) acc[e] = 0.0f;
            float mx[NN];
#pragma unroll
            for (int n = 0; n < NN; n++) mx[n] = -3.4e38f;

            for (int t = t0 + w; t < t0 + TQ; t += NW) {
                const float* fp = fq + ((size_t)bq * TT + t) * CC + 4 * lane;
                float fv[12];
#pragma unroll
                for (int j = 0; j < 3; j++) {
                    float4 u = *(const float4*)(fp + 128 * j);
                    fv[4*j] = u.x; fv[4*j+1] = u.y; fv[4*j+2] = u.z; fv[4*j+3] = u.w;
                }
                float r[11];
#pragma unroll
                for (int k = 0; k < 11; k++) r[k] = 0.0f;
#pragma unroll
                for (int e = 0; e < 12; e++) r[0] += fv[e] * fv[e];
#pragma unroll
                for (int n = 0; n < NN; n++) {
                    const float* fsp = fshot + (((size_t)(b * NN + n)) * KT + t) * CC + 4 * lane;
#pragma unroll
                    for (int j = 0; j < 3; j++) {
                        float4 u = *(const float4*)(fsp + 128 * j);
                        r[1 + n] += fv[4*j]*u.x + fv[4*j+1]*u.y + fv[4*j+2]*u.z + fv[4*j+3]*u.w;
                    }
                }
#pragma unroll
                for (int n = 0; n < NN; n++) {
#pragma unroll
                    for (int j = 0; j < 3; j++) {
                        float4 u = *(const float4*)(&sm.m.vv[n * CC + 128 * j + 4 * lane]);
                        r[6 + n] += fv[4*j]*u.x + fv[4*j+1]*u.y + fv[4*j+2]*u.z + fv[4*j+3]*u.w;
                    }
                }
                warpRed<11>(r);
                float nq = sqrtf(r[0]);
                int trel = t - t0;
#pragma unroll
                for (int n = 0; n < NN; n++) {
                    float den = fmaxf(nq * sm.m.nss[n * TQ + trel], 1e-8f);
                    mx[n] = fmaxf(mx[n], r[1 + n] / den);
                    float mq = sigm(r[6 + n]);
#pragma unroll
                    for (int e = 0; e < 12; e++) acc[n * 12 + e] += fv[e] * mq;
                }
            }

#pragma unroll
            for (int n = 0; n < NN; n++) {
#pragma unroll
                for (int e = 0; e < 12; e++) {
                    int c = 128 * (e >> 2) + (lane << 2) + (e & 3);
                    atomicAdd(&sm.m.accq[n * CC + c], acc[n * 12 + e]);
                }
            }
            if (lane == 0) {
#pragma unroll
                for (int n = 0; n < NN; n++) sm.m.wmax[w * NN + n] = mx[n];
            }
            __syncthreads();

            size_t base = ((size_t)(chunk * BQ + bq)) * NN * CC;
            for (int i = tid; i < NN * CC; i += 384)
                g_accq_part[base + i] = sm.m.accq[i];
            if (tid < NN) {
                float mm = -3.4e38f;
#pragma unroll
                for (int ww = 0; ww < NW; ww++) mm = fmaxf(mm, sm.m.wmax[ww * NN + tid]);
                g_mx_part[(chunk * BQ + bq) * NN + tid] = mm;
            }
            __syncthreads();
        }
    }
    gridBar();

    // ============ Phase 5: final outputs ============
    for (int bq = blockIdx.x; bq < BQ; bq += gridDim.x) {
        int b = bq / QQ;
        __syncthreads();
        if (tid == 0) {
            float s = 0.0f;
#pragma unroll
            for (int n = 0; n < NN; n++) {
                float mm = -3.4e38f;
#pragma unroll
                for (int ch = 0; ch < NCHK; ch++)
                    mm = fmaxf(mm, g_mx_part[(ch * BQ + bq) * NN + n]);
                s += mm;
            }
            s *= (1.0f / NN);
            out[bq] = s;
            out[BQ + bq] = s;
        }
        float xqv = xq_in[(size_t)bq * CC + tid];
        float pv[16];
        pv[0] = xqv * xqv;
#pragma unroll
        for (int n = 0; n < NN; n++) {
            float a = 0.0f;
#pragma unroll
            for (int ch = 0; ch < NCHK; ch++)
                a += g_accq_part[((size_t)(ch * BQ + bq) * NN + n) * CC + tid];
            float xqr = g_wc[(b * NN + n) * CC + tid] * a * (1.0f / TT);
            pv[1 + n]  = xqv * g_xs2_hat[(b * NN + n) * CC + tid];
            pv[6 + n]  = xqr * xqr;
            pv[11 + n] = xqr * g_xs_hat[(b * NN + n) * CC + tid];
        }
        warpRed<16>(pv);
        if (lane == 0) {
#pragma unroll
            for (int k = 0; k < 16; k++) sm.r.cw[w][k] = pv[k];
        }
        __syncthreads();
        if (tid < 16) {
            float s = 0.0f;
#pragma unroll
            for (int ww = 0; ww < NW; ww++) s += sm.r.cw[ww][tid];
            sm.r.tot[tid] = s;
        }
        __syncthreads();
        if (tid < NN) {
            float nq2 = sqrtf(sm.r.tot[0]);
            out[2 * BQ + bq * NN + tid] = TEMPF * sm.r.tot[1 + tid] / fmaxf(nq2, 1e-12f);
            out[2 * BQ + BQ * NN + bq * NN + tid] =
                sm.r.tot[11 + tid] / (1e-16f + sqrtf(sm.r.tot[6 + tid]));
        }
        __syncthreads();
    }
}

extern "C" void kernel_launch(void* const* d_in, const int* in_sizes, int n_in,
                              void* d_out, int out_size) {
    const float* feat_shot  = (const float*)d_in[0];
    const float* feat_query = (const float*)d_in[1];
    const float* x_shot     = (const float*)d_in[2];
    const float* x_query    = (const float*)d_in[3];
    const float* w1_task    = (const float*)d_in[4];
    const float* b1_task    = (const float*)d_in[5];
    const float* w2_task    = (const float*)d_in[6];
    const float* b2_task    = (const float*)d_in[7];
    const float* w1_cls     = (const float*)d_in[8];
    const float* b1_cls     = (const float*)d_in[9];
    const float* w2_cls     = (const float*)d_in[10];
    const float* b2_cls     = (const float*)d_in[11];
    float* out = (float*)d_out;

    int dev = 0;
    cudaGetDevice(&dev);
    int sms = 0;
    cudaDeviceGetAttribute(&sms, cudaDevAttrMultiProcessorCount, dev);
    int maxBlk = 1;
    cudaOccupancyMaxActiveBlocksPerMultiprocessor(&maxBlk, kFused, 384, 0);
    if (maxBlk < 1) maxBlk = 1;
    int grid = sms * maxBlk;

    kFused<<<grid, 384>>>(feat_shot, feat_query, x_shot, x_query,
                          w1_task, b1_task, w2_task, b2_task,
                          w1_cls, b1_cls, w2_cls, b2_cls, out);
}

// round 4
// speedup vs baseline: 1.1902x; 1.0136x over previous
#include <cuda_runtime.h>
#include <math.h>

#define BB 2
#define QQ 75
#define NN 5
#define KK 1
#define TT 196
#define CC 384
#define HH 1536
#define KT 196
#define BQ 150
#define TEMPF 10.0f

#define MCH 7          // t-chunks for mean partials (28 rows)
#define SCH 5          // t-chunks for shot pass (40/36 rows)
#define HCH 8          // hidden chunks for MLP (192 units)
#define HCW 192
#define NCHK 7         // t-chunks for main pass
#define TQ 28          // TT / NCHK
#define NW 12          // warps per block (384 threads)

// ---------------- persistent scratch ----------------
__device__ float g_mean_part[BB*NN*MCH*CC];
__device__ float g_mlp_part[(BB + BB*NN)*HCH*CC];
__device__ float g_wt[BB*CC];
__device__ float g_wc[BB*NN*CC];
__device__ float g_ns[BB*NN*KT];
__device__ float g_shot_part[BB*NN*SCH*CC];
__device__ float g_xs_hat[BB*NN*CC];
__device__ float g_xs2_hat[BB*NN*CC];
__device__ float g_accq_part[NCHK*BQ*NN*CC];
__device__ float g_mx_part[NCHK*BQ*NN];
__device__ unsigned g_bar_cnt;   // returns to 0 after every barrier
__device__ unsigned g_bar_gen;   // monotonic across replays (wrap-safe)

template<int NV>
__device__ __forceinline__ void warpRed(float* v) {
#pragma unroll
    for (int off = 16; off; off >>= 1) {
#pragma unroll
        for (int k = 0; k < NV; k++)
            v[k] += __shfl_xor_sync(0xffffffffu, v[k], off);
    }
}

__device__ __forceinline__ float sigm(float x) {
    return 1.0f / (1.0f + __expf(-x));
}

// device-wide barrier: all blocks co-resident (grid sized by occupancy API)
__device__ __forceinline__ void gridBar() {
    __syncthreads();
    if (threadIdx.x == 0) {
        __threadfence();
        unsigned gen = *(volatile unsigned*)&g_bar_gen;
        if (atomicAdd(&g_bar_cnt, 1u) == gridDim.x - 1u) {
            g_bar_cnt = 0u;
            __threadfence();
            atomicAdd(&g_bar_gen, 1u);
        } else {
            while (*(volatile unsigned*)&g_bar_gen == gen) __nanosleep(64);
        }
        __threadfence();
    }
    __syncthreads();
}

struct SmemMain { float vv[NN*CC]; float nss[NN*TQ]; float smq[NN*TQ]; float wmax[NW*NN]; };
struct SmemMLP  { float sx[CC]; float hp[2*HCW]; float hid[HCW]; };
struct SmemShot { float vv[CC]; float accs[CC]; };
struct SmemRed  { float cw[NW][16]; float tot[16]; };
union SmemU { SmemMain m; SmemMLP p; SmemShot s; SmemRed r; };

__global__ __launch_bounds__(384, 2) void kFused(
    const float* __restrict__ fshot, const float* __restrict__ fq,
    const float* __restrict__ x_shot, const float* __restrict__ xq_in,
    const float* __restrict__ w1t, const float* __restrict__ b1t,
    const float* __restrict__ w2t, const float* __restrict__ b2t,
    const float* __restrict__ w1c, const float* __restrict__ b1c,
    const float* __restrict__ w2c, const float* __restrict__ b2c,
    float* __restrict__ out) {
    __shared__ SmemU sm;
    const int tid = threadIdx.x;
    const int w = tid >> 5, lane = tid & 31;

    // ============ Phase 1: shot mean partials + plain prototype ============
    for (int task = blockIdx.x; task < BB*NN*MCH + BB*NN; task += gridDim.x) {
        if (task < BB*NN*MCH) {
            int bn = task / MCH, ch = task % MCH;
            int t0 = ch * 28;
            const float* p = fshot + ((size_t)bn * KT + t0) * CC + tid;
            float s = 0.0f;
#pragma unroll 4
            for (int t = 0; t < 28; t++) s += p[(size_t)t * CC];
            g_mean_part[(bn * MCH + ch) * CC + tid] = s;
        } else {
            int bn = task - BB*NN*MCH;
            __syncthreads();
            float xm = x_shot[(size_t)bn * CC + tid];  // KK=1
            float r[1] = {xm * xm};
            warpRed<1>(r);
            if (lane == 0) sm.r.cw[w][0] = r[0];
            __syncthreads();
            float tot = 0.0f;
#pragma unroll
            for (int ww = 0; ww < NW; ww++) tot += sm.r.cw[ww][0];
            g_xs2_hat[bn * CC + tid] = xm / fmaxf(sqrtf(tot), 1e-12f);
            __syncthreads();
        }
    }
    gridBar();

    // ============ Phase 2: MLP partials (means reconstructed inline) ============
    for (int task = blockIdx.x; task < (BB + BB*NN) * HCH; task += gridDim.x) {
        int row = task / HCH, ch = task % HCH;
        const float *w1, *b1, *w2;
        __syncthreads();
        if (row < BB) {
            w1 = w1t; b1 = b1t; w2 = w2t;
            float s = 0.0f;
#pragma unroll
            for (int n = 0; n < NN; n++)
#pragma unroll
                for (int c2 = 0; c2 < MCH; c2++)
                    s += g_mean_part[((row * NN + n) * MCH + c2) * CC + tid];
            sm.p.sx[tid] = s * (1.0f / (KT * NN));
        } else {
            int r = row - BB;
            w1 = w1c; b1 = b1c; w2 = w2c;
            float s = 0.0f;
#pragma unroll
            for (int c2 = 0; c2 < MCH; c2++)
                s += g_mean_part[(r * MCH + c2) * CC + tid];
            sm.p.sx[tid] = s * (1.0f / KT);
        }
        __syncthreads();

        int half = tid / HCW, jj = tid % HCW, j0 = ch * HCW;
        float h = 0.0f;
        const float* w1p = w1 + (size_t)(half * HCW) * HH + j0 + jj;
#pragma unroll 4
        for (int c = 0; c < HCW; c++) h += sm.p.sx[half * HCW + c] * w1p[(size_t)c * HH];
        sm.p.hp[half * HCW + jj] = h;
        __syncthreads();
        if (tid < HCW) sm.p.hid[tid] = fmaxf(sm.p.hp[tid] + sm.p.hp[HCW + tid] + b1[j0 + tid], 0.0f);
        __syncthreads();

        float o = 0.0f;
        const float* w2p = w2 + (size_t)j0 * CC + tid;
#pragma unroll 4
        for (int j = 0; j < HCW; j++) o += sm.p.hid[j] * w2p[(size_t)j * CC];
        g_mlp_part[(size_t)task * CC + tid] = o;
        __syncthreads();
    }
    gridBar();

    // ============ Phase 3: shot pass (ns + map_s partials) + MLP finish ============
    for (int task = blockIdx.x; task < BB*NN*SCH + BB + BB*NN; task += gridDim.x) {
        if (task < BB*NN*SCH) {
            int bn = task / SCH, ch = task % SCH;
            int b = bn / NN;
            int t0 = ch * 40, t1 = min(KT, t0 + 40);
            __syncthreads();
            {   // vv = wc * wt reconstructed from MLP partials
                float ot = b2t[tid], oc = b2c[tid];
#pragma unroll
                for (int c2 = 0; c2 < HCH; c2++) {
                    ot += g_mlp_part[(size_t)(b * HCH + c2) * CC + tid];
                    oc += g_mlp_part[(size_t)((BB + bn) * HCH + c2) * CC + tid];
                }
                sm.s.vv[tid] = sigm(oc) * ot;
                sm.s.accs[tid] = 0.0f;
            }
            __syncthreads();

            float acc[12];
#pragma unroll
            for (int e = 0; e < 12; e++) acc[e] = 0.0f;
            for (int t = t0 + w; t < t1; t += NW) {
                const float* fp = fshot + ((size_t)bn * KT + t) * CC + 4 * lane;
                float fv[12];
#pragma unroll
                for (int j = 0; j < 3; j++) {
                    float4 u = *(const float4*)(fp + 128 * j);
                    fv[4*j] = u.x; fv[4*j+1] = u.y; fv[4*j+2] = u.z; fv[4*j+3] = u.w;
                }
                float r[2] = {0.0f, 0.0f};
#pragma unroll
                for (int j = 0; j < 3; j++) {
                    float4 u = *(const float4*)(&sm.s.vv[128 * j + 4 * lane]);
                    r[0] += fv[4*j]*fv[4*j] + fv[4*j+1]*fv[4*j+1] + fv[4*j+2]*fv[4*j+2] + fv[4*j+3]*fv[4*j+3];
                    r[1] += fv[4*j]*u.x + fv[4*j+1]*u.y + fv[4*j+2]*u.z + fv[4*j+3]*u.w;
                }
                warpRed<2>(r);
                if (lane == 0) g_ns[bn * KT + t] = sqrtf(r[0]);
                float ms = sigm(r[1]);
#pragma unroll
                for (int e = 0; e < 12; e++) acc[e] += fv[e] * ms;
            }
#pragma unroll
            for (int e = 0; e < 12; e++) {
                int c = 128 * (e >> 2) + (lane << 2) + (e & 3);
                atomicAdd(&sm.s.accs[c], acc[e]);
            }
            __syncthreads();
            g_shot_part[(size_t)task * CC + tid] = sm.s.accs[tid];
            __syncthreads();
        } else {
            int row = task - BB*NN*SCH;
            float o = (row < BB) ? b2t[tid] : b2c[tid];
#pragma unroll
            for (int c2 = 0; c2 < HCH; c2++) o += g_mlp_part[(size_t)(row * HCH + c2) * CC + tid];
            if (row < BB) g_wt[row * CC + tid] = o;
            else          g_wc[(row - BB) * CC + tid] = sigm(o);
        }
    }
    gridBar();

    // ============ Phase 4: reweighted prototype finish + main fused pass ============
    for (int task = blockIdx.x; task < BB*NN + BQ*NCHK; task += gridDim.x) {
        if (task < BB*NN) {
            int bn = task;
            __syncthreads();
            float s = 0.0f;
#pragma unroll
            for (int ch = 0; ch < SCH; ch++) s += g_shot_part[(size_t)(bn * SCH + ch) * CC + tid];
            float xsr = g_wc[bn * CC + tid] * s * (1.0f / KT);
            float r[1] = {xsr * xsr};
            warpRed<1>(r);
            if (lane == 0) sm.r.cw[w][0] = r[0];
            __syncthreads();
            float tot = 0.0f;
#pragma unroll
            for (int ww = 0; ww < NW; ww++) tot += sm.r.cw[ww][0];
            g_xs_hat[bn * CC + tid] = xsr / (1e-16f + sqrtf(tot));
            __syncthreads();
        } else {
            int m = task - BB*NN;
            int bq = m / NCHK, chunk = m % NCHK;
            int b = bq / QQ;
            int t0 = chunk * TQ;
            __syncthreads();
            {
                float wtb = g_wt[b * CC + tid];
#pragma unroll
                for (int n = 0; n < NN; n++)
                    sm.m.vv[n * CC + tid] = g_wc[(b * NN + n) * CC + tid] * wtb;
                for (int i = tid; i < NN * TQ; i += 384) {
                    int n = i / TQ, tt = i % TQ;
                    sm.m.nss[i] = g_ns[(b * NN + n) * KT + t0 + tt];
                }
            }
            __syncthreads();

            float mx[NN];
#pragma unroll
            for (int n = 0; n < NN; n++) mx[n] = -3.4e38f;

            // ---- Pass A: warp-per-t, compute dots, store mq to smem ----
            for (int trel = w; trel < TQ; trel += NW) {
                const float* fp = fq + ((size_t)bq * TT + t0 + trel) * CC + 4 * lane;
                float fv[12];
#pragma unroll
                for (int j = 0; j < 3; j++) {
                    float4 u = *(const float4*)(fp + 128 * j);
                    fv[4*j] = u.x; fv[4*j+1] = u.y; fv[4*j+2] = u.z; fv[4*j+3] = u.w;
                }
                float r[11];
#pragma unroll
                for (int k = 0; k < 11; k++) r[k] = 0.0f;
#pragma unroll
                for (int e = 0; e < 12; e++) r[0] += fv[e] * fv[e];
#pragma unroll
                for (int n = 0; n < NN; n++) {
                    const float* fsp = fshot + (((size_t)(b * NN + n)) * KT + t0 + trel) * CC + 4 * lane;
#pragma unroll
                    for (int j = 0; j < 3; j++) {
                        float4 u = *(const float4*)(fsp + 128 * j);
                        r[1 + n] += fv[4*j]*u.x + fv[4*j+1]*u.y + fv[4*j+2]*u.z + fv[4*j+3]*u.w;
                    }
                }
#pragma unroll
                for (int n = 0; n < NN; n++) {
#pragma unroll
                    for (int j = 0; j < 3; j++) {
                        float4 u = *(const float4*)(&sm.m.vv[n * CC + 128 * j + 4 * lane]);
                        r[6 + n] += fv[4*j]*u.x + fv[4*j+1]*u.y + fv[4*j+2]*u.z + fv[4*j+3]*u.w;
                    }
                }
                warpRed<11>(r);
                float nq = sqrtf(r[0]);
#pragma unroll
                for (int n = 0; n < NN; n++) {
                    float den = fmaxf(nq * sm.m.nss[n * TQ + trel], 1e-8f);
                    mx[n] = fmaxf(mx[n], r[1 + n] / den);
                }
                if (lane == 0) {
#pragma unroll
                    for (int n = 0; n < NN; n++)
                        sm.m.smq[n * TQ + trel] = sigm(r[6 + n]);
                }
            }
            if (lane == 0) {
#pragma unroll
                for (int n = 0; n < NN; n++) sm.m.wmax[w * NN + n] = mx[n];
            }
            __syncthreads();

            // ---- Pass B: thread-per-c accq accumulation (fq L1-resident) ----
            {
                float acc[NN];
#pragma unroll
                for (int n = 0; n < NN; n++) acc[n] = 0.0f;
                const float* fcol = fq + ((size_t)bq * TT + t0) * CC + tid;
#pragma unroll 4
                for (int trel = 0; trel < TQ; trel++) {
                    float fv = fcol[(size_t)trel * CC];
#pragma unroll
                    for (int n = 0; n < NN; n++)
                        acc[n] += fv * sm.m.smq[n * TQ + trel];
                }
                size_t base = ((size_t)(chunk * BQ + bq)) * NN * CC;
#pragma unroll
                for (int n = 0; n < NN; n++)
                    g_accq_part[base + n * CC + tid] = acc[n];
            }
            if (tid < NN) {
                float mm = -3.4e38f;
#pragma unroll
                for (int ww = 0; ww < NW; ww++) mm = fmaxf(mm, sm.m.wmax[ww * NN + tid]);
                g_mx_part[(chunk * BQ + bq) * NN + tid] = mm;
            }
            __syncthreads();
        }
    }
    gridBar();

    // ============ Phase 5: final outputs ============
    for (int bq = blockIdx.x; bq < BQ; bq += gridDim.x) {
        int b = bq / QQ;
        __syncthreads();
        if (tid == 0) {
            float s = 0.0f;
#pragma unroll
            for (int n = 0; n < NN; n++) {
                float mm = -3.4e38f;
#pragma unroll
                for (int ch = 0; ch < NCHK; ch++)
                    mm = fmaxf(mm, g_mx_part[(ch * BQ + bq) * NN + n]);
                s += mm;
            }
            s *= (1.0f / NN);
            out[bq] = s;
            out[BQ + bq] = s;
        }
        float xqv = xq_in[(size_t)bq * CC + tid];
        float pv[16];
        pv[0] = xqv * xqv;
#pragma unroll
        for (int n = 0; n < NN; n++) {
            float a = 0.0f;
#pragma unroll
            for (int ch = 0; ch < NCHK; ch++)
                a += g_accq_part[((size_t)(ch * BQ + bq) * NN + n) * CC + tid];
            float xqr = g_wc[(b * NN + n) * CC + tid] * a * (1.0f / TT);
            pv[1 + n]  = xqv * g_xs2_hat[(b * NN + n) * CC + tid];
            pv[6 + n]  = xqr * xqr;
            pv[11 + n] = xqr * g_xs_hat[(b * NN + n) * CC + tid];
        }
        warpRed<16>(pv);
        if (lane == 0) {
#pragma unroll
            for (int k = 0; k < 16; k++) sm.r.cw[w][k] = pv[k];
        }
        __syncthreads();
        if (tid < 16) {
            float s = 0.0f;
#pragma unroll
            for (int ww = 0; ww < NW; ww++) s += sm.r.cw[ww][tid];
            sm.r.tot[tid] = s;
        }
        __syncthreads();
        if (tid < NN) {
            float nq2 = sqrtf(sm.r.tot[0]);
            out[2 * BQ + bq * NN + tid] = TEMPF * sm.r.tot[1 + tid] / fmaxf(nq2, 1e-12f);
            out[2 * BQ + BQ * NN + bq * NN + tid] =
                sm.r.tot[11 + tid] / (1e-16f + sqrtf(sm.r.tot[6 + tid]));
        }
        __syncthreads();
    }
}

extern "C" void kernel_launch(void* const* d_in, const int* in_sizes, int n_in,
                              void* d_out, int out_size) {
    const float* feat_shot  = (const float*)d_in[0];
    const float* feat_query = (const float*)d_in[1];
    const float* x_shot     = (const float*)d_in[2];
    const float* x_query    = (const float*)d_in[3];
    const float* w1_task    = (const float*)d_in[4];
    const float* b1_task    = (const float*)d_in[5];
    const float* w2_task    = (const float*)d_in[6];
    const float* b2_task    = (const float*)d_in[7];
    const float* w1_cls     = (const float*)d_in[8];
    const float* b1_cls     = (const float*)d_in[9];
    const float* w2_cls     = (const float*)d_in[10];
    const float* b2_cls     = (const float*)d_in[11];
    float* out = (float*)d_out;

    int dev = 0;
    cudaGetDevice(&dev);
    int sms = 0;
    cudaDeviceGetAttribute(&sms, cudaDevAttrMultiProcessorCount, dev);
    int maxBlk = 1;
    cudaOccupancyMaxActiveBlocksPerMultiprocessor(&maxBlk, kFused, 384, 0);
    if (maxBlk < 1) maxBlk = 1;
    int grid = sms * maxBlk;

    kFused<<<grid, 384>>>(feat_shot, feat_query, x_shot, x_query,
                          w1_task, b1_task, w2_task, b2_task,
                          w1_cls, b1_cls, w2_cls, b2_cls, out);
}